// round 3
// baseline (speedup 1.0000x reference)
#include <cuda_runtime.h>

// Entmax (alpha=1.5) per row, B=2048 x N=32000 fp32.
// v3: streaming 2-pass + L2 re-read + scatter epilogue.
//   pass1: read row (L2-resident) -> rowmax, while zero-filling output.
//   pass2: re-read from L2, filter candidates z > rowmax-1 (~15/row).
//   Newton on candidates (warp 0). Kernel 2 scatters nonzeros over zeros.
// 512 threads/CTA, ~32 regs -> 3-4 CTAs/SM: memory stays saturated.

#define NC      32000
#define NV      (NC / 4)
#define TPB     512
#define CAP     512
#define NEG     (-1e30f)
#define MAXROWS 4096

__device__ float g_tau[MAXROWS];
__device__ int   g_cnt[MAXROWS];
__device__ int   g_idx[MAXROWS][CAP];
__device__ float g_val[MAXROWS][CAP];

__global__ __launch_bounds__(TPB, 3)
void entmax_phase1(const float* __restrict__ z, float* __restrict__ out) {
    __shared__ float s_f[16];
    __shared__ float s_g[16];
    __shared__ int   s_i[16];
    __shared__ float s_cval[CAP];
    __shared__ int   s_cidx[CAP];
    __shared__ int   s_cnt;
    __shared__ float s_tau0, s_vmax, s_tauref;
    __shared__ int   s_bK;
    __shared__ float s_bS, s_bV;

    const int tid  = threadIdx.x;
    const int lane = tid & 31;
    const int wid  = tid >> 5;
    const int row  = blockIdx.x;
    const long long base = (long long)row * NC;
    const float4* zr   = (const float4*)(z + base);
    float4*       orow = (float4*)(out + base);

    // ---- pass 1: rowmax + zero-fill output (independent -> overlapped) ----
    float lmax = NEG;
    const float4 zero4 = make_float4(0.f, 0.f, 0.f, 0.f);
    for (int f = tid; f < NV; f += TPB) {
        const float4 v = __ldcg(&zr[f]);
        __stcs(&orow[f], zero4);
        lmax = fmaxf(lmax, fmaxf(fmaxf(v.x, v.y), fmaxf(v.z, v.w)));
    }
    #pragma unroll
    for (int o = 16; o; o >>= 1)
        lmax = fmaxf(lmax, __shfl_xor_sync(0xffffffffu, lmax, o));
    if (lane == 0) s_f[wid] = lmax;
    if (tid == 0) s_cnt = 0;
    __syncthreads();
    if (tid < 32) {
        float m = (tid < 16) ? s_f[tid] : NEG;
        #pragma unroll
        for (int o = 16; o; o >>= 1)
            m = fmaxf(m, __shfl_xor_sync(0xffffffffu, m, o));
        if (tid == 0) s_tau0 = m - 1.0f;
    }
    __syncthreads();
    const float tau0 = s_tau0;

    // ---- pass 2: re-read from L2, filter candidates, vmax of rejects ----
    float vmax = NEG;
    for (int f = tid; f < NV; f += TPB) {
        const float4 v = __ldcg(&zr[f]);
        const int e = f * 4;
        float c;
        c = v.x; if (c > tau0) { int p = atomicAdd(&s_cnt, 1); if (p < CAP) { s_cval[p] = c; s_cidx[p] = e + 0; } } else vmax = fmaxf(vmax, c);
        c = v.y; if (c > tau0) { int p = atomicAdd(&s_cnt, 1); if (p < CAP) { s_cval[p] = c; s_cidx[p] = e + 1; } } else vmax = fmaxf(vmax, c);
        c = v.z; if (c > tau0) { int p = atomicAdd(&s_cnt, 1); if (p < CAP) { s_cval[p] = c; s_cidx[p] = e + 2; } } else vmax = fmaxf(vmax, c);
        c = v.w; if (c > tau0) { int p = atomicAdd(&s_cnt, 1); if (p < CAP) { s_cval[p] = c; s_cidx[p] = e + 3; } } else vmax = fmaxf(vmax, c);
    }
    #pragma unroll
    for (int o = 16; o; o >>= 1)
        vmax = fmaxf(vmax, __shfl_xor_sync(0xffffffffu, vmax, o));
    if (lane == 0) s_g[wid] = vmax;
    __syncthreads();
    if (tid < 32) {
        float m = (tid < 16) ? s_g[tid] : NEG;
        #pragma unroll
        for (int o = 16; o; o >>= 1)
            m = fmaxf(m, __shfl_xor_sync(0xffffffffu, m, o));
        if (tid == 0) s_vmax = m;
    }
    __syncthreads();
    const int cnt = s_cnt;

    if (cnt <= CAP) {
        // ---- fast path: warp 0 Newton on the candidate set ----
        if (wid == 0) {
            float tl = tau0;
            int   kp = -1;
            int   kF = 1; float SF = 0.0f; float vcF = NEG;
            for (int itr = 0; itr < 64; ++itr) {
                int k = 0; float S = 0.0f; float vc = NEG;
                for (int i = lane; i < cnt; i += 32) {
                    const float c = s_cval[i];
                    if (c > tl) { k++; S += c; } else vc = fmaxf(vc, c);
                }
                #pragma unroll
                for (int o = 16; o; o >>= 1) {
                    k += __shfl_xor_sync(0xffffffffu, k, o);
                    S += __shfl_xor_sync(0xffffffffu, S, o);
                    vc = fmaxf(vc, __shfl_xor_sync(0xffffffffu, vc, o));
                }
                kF = k; SF = S; vcF = vc;
                if (k == kp) break;            // support fixed point
                kp = k;
                tl = (S - 1.0f) / (float)k;
            }
            // reference quirk: cs_k = cs[k_max] = S + max{z <= tau_final}
            const float vfin = fmaxf(vcF, s_vmax);
            const float vt = (vfin > -1e29f) ? vfin : 0.0f;
            if (lane == 0) {
                const float tr = (SF + vt - 1.0f) / (float)kF;
                g_tau[row] = tr;
                g_cnt[row] = cnt;
            }
        }
        __syncthreads();
        for (int i = tid; i < cnt; i += TPB) {
            g_idx[row][i] = s_cidx[i];
            g_val[row][i] = s_cval[i];
        }
    } else {
        // ---- fallback (pathological rows): block Newton with L2 re-reads ----
        float tau = tau0;
        int kprev = -1;
        float tau_ref;
        for (int it = 0; it < 64; ++it) {
            int k = 0; float S = 0.0f; float v = NEG;
            for (int f = tid; f < NV; f += TPB) {
                const float4 w4 = __ldcg(&zr[f]);
                float c;
                c = w4.x; if (c > tau) { k++; S += c; } else v = fmaxf(v, c);
                c = w4.y; if (c > tau) { k++; S += c; } else v = fmaxf(v, c);
                c = w4.z; if (c > tau) { k++; S += c; } else v = fmaxf(v, c);
                c = w4.w; if (c > tau) { k++; S += c; } else v = fmaxf(v, c);
            }
            #pragma unroll
            for (int o = 16; o; o >>= 1) {
                k += __shfl_xor_sync(0xffffffffu, k, o);
                S += __shfl_xor_sync(0xffffffffu, S, o);
                v  = fmaxf(v, __shfl_xor_sync(0xffffffffu, v, o));
            }
            if (lane == 0) { s_i[wid] = k; s_f[wid] = S; s_g[wid] = v; }
            __syncthreads();
            if (tid < 32) {
                int   kk = (tid < 16) ? s_i[tid] : 0;
                float SS = (tid < 16) ? s_f[tid] : 0.0f;
                float vv = (tid < 16) ? s_g[tid] : NEG;
                #pragma unroll
                for (int o = 16; o; o >>= 1) {
                    kk += __shfl_xor_sync(0xffffffffu, kk, o);
                    SS += __shfl_xor_sync(0xffffffffu, SS, o);
                    vv  = fmaxf(vv, __shfl_xor_sync(0xffffffffu, vv, o));
                }
                if (tid == 0) { s_bK = kk; s_bS = SS; s_bV = vv; }
            }
            __syncthreads();
            const int   K  = s_bK;
            const float Sa = s_bS;
            const float Va = s_bV;
            if (K == kprev || it == 63) {
                const float vt = (Va > -1e29f) ? Va : 0.0f;
                tau_ref = (Sa + vt - 1.0f) / (float)K;
                break;
            }
            kprev = K;
            tau = (Sa - 1.0f) / (float)K;
            __syncthreads();
        }
        // full rewrite; SAME f mapping as the zero-fill -> per-thread program
        // order guarantees final values.
        for (int f = tid; f < NV; f += TPB) {
            const float4 v = __ldcg(&zr[f]);
            float a = fmaxf(v.x - tau_ref, 0.0f);
            float b = fmaxf(v.y - tau_ref, 0.0f);
            float c = fmaxf(v.z - tau_ref, 0.0f);
            float d = fmaxf(v.w - tau_ref, 0.0f);
            float4 o;
            o.x = a * sqrtf(a); o.y = b * sqrtf(b);
            o.z = c * sqrtf(c); o.w = d * sqrtf(d);
            __stcs(&orow[f], o);
        }
        if (tid == 0) g_cnt[row] = 0;   // scatter kernel: no-op for this row
    }
}

__global__ void entmax_phase2(float* __restrict__ out, int rows) {
    const int w    = (blockIdx.x * blockDim.x + threadIdx.x) >> 5;
    const int lane = threadIdx.x & 31;
    if (w >= rows) return;
    int n = g_cnt[w];
    if (n <= 0) return;
    if (n > CAP) n = CAP;
    const float tau = g_tau[w];
    float* orow = out + (long long)w * NC;
    for (int i = lane; i < n; i += 32) {
        const float r = g_val[w][i] - tau;
        if (r > 0.0f) orow[g_idx[w][i]] = r * sqrtf(r);
    }
}

extern "C" void kernel_launch(void* const* d_in, const int* in_sizes, int n_in,
                              void* d_out, int out_size) {
    const float* z = (const float*)d_in[0];
    float* out = (float*)d_out;
    const int rows = in_sizes[0] / NC;
    entmax_phase1<<<rows, TPB>>>(z, out);
    const int warps_per_blk = 256 / 32;
    const int blocks2 = (rows + warps_per_blk - 1) / warps_per_blk;
    entmax_phase2<<<blocks2, 256>>>(out, rows);
}